// round 1
// baseline (speedup 1.0000x reference)
#include <cuda_runtime.h>
#include <cstddef>

#define FULLMASK 0xffffffffu

// T=128, D=768, HID=768, L=3, OUT=768, LH=2304
// Scratch (static __device__ arrays: allocation-free per harness rules)
__device__ float g_H[128 * 2304];       // h_cat per step (scan output)
__device__ float g_wfT[2304 * 768];     // transposed w_final
__device__ float g_part[6 * 128 * 768]; // split-K partials for readout GEMM

// ---------------------------------------------------------------- helpers
__device__ __forceinline__ unsigned smem_u32(const void* p) {
    unsigned a;
    asm("{ .reg .u64 t; cvta.to.shared.u64 t, %1; cvt.u32.u64 %0, t; }"
        : "=r"(a) : "l"(p));
    return a;
}
__device__ __forceinline__ void cp_async16(void* dst, const void* src) {
    unsigned d = smem_u32(dst);
    asm volatile("cp.async.ca.shared.global [%0], [%1], 16;\n" :: "r"(d), "l"(src));
}
__device__ __forceinline__ void cp_commit() { asm volatile("cp.async.commit_group;\n" ::); }
__device__ __forceinline__ void cp_wait0()  { asm volatile("cp.async.wait_group 0;\n" ::); }

__device__ __forceinline__ float sigmoidf_(float z) {
    return 1.0f / (1.0f + __expf(-z));
}

// ---------------------------------------------------------------- kernel A: wf transpose
// wf: [768][2304] -> g_wfT: [2304][768]
__global__ void __launch_bounds__(256) k_transpose(const float* __restrict__ wf) {
    __shared__ float tile[32][33];
    const int j0 = blockIdx.x * 32;   // 0..2303 (72 blocks)
    const int o0 = blockIdx.y * 32;   // 0..767  (24 blocks)
    const int tx = threadIdx.x & 31, ty = threadIdx.x >> 5;  // 32x8
#pragma unroll
    for (int i = 0; i < 4; i++)
        tile[ty + 8 * i][tx] = wf[(size_t)(o0 + ty + 8 * i) * 2304 + (j0 + tx)];
    __syncthreads();
#pragma unroll
    for (int i = 0; i < 4; i++)
        g_wfT[(size_t)(j0 + ty + 8 * i) * 768 + (o0 + tx)] = tile[tx][ty + 8 * i];
}

// ---------------------------------------------------------------- kernel B: the scan
// 144 CTAs. CTA j: layer l=j/48, rows [(j%48)*16, +16). 256 threads:
// warp w owns local rows 2w,2w+1; lane owns cols {lane+32k, k<24}.
// P and eta (or W for the 'M' layer) live in registers for the whole scan.
__global__ void __launch_bounds__(256) k_scan(
    const float* __restrict__ x_seq, const float* __restrict__ W,
    const float* __restrict__ b, const float* __restrict__ lam,
    const float* __restrict__ eta0, const float* __restrict__ eta1p,
    const float* __restrict__ eta2, const float* __restrict__ P_init)
{
    __shared__ float wxb[2048];                      // 128 t x 16 rows : W@x + b
    __shared__ __align__(16) float xb[2][4][768];    // x double buffer (also precompute staging)

    const int cta = blockIdx.x;
    const int l   = cta / 48;
    const int rb  = (cta % 48) * 16;
    const bool isM = (l == 1);                       // TYPES = (A, M, A)
    const int tid = threadIdx.x;
    const int w = tid >> 5, lane = tid & 31;
    const int r0 = 2 * w, r1 = r0 + 1;
    const int gr0 = rb + r0, gr1 = rb + r1;          // rows within layer
    const float* Wl = W + (size_t)l * 589824;

    // ---- load W rows (registers) for WXB precompute
    float wv0[24], wv1[24];
#pragma unroll
    for (int k = 0; k < 24; k++) {
        wv0[k] = Wl[(size_t)gr0 * 768 + lane + 32 * k];
        wv1[k] = Wl[(size_t)gr1 * 768 + lane + 32 * k];
    }
    const float bb0 = b[l * 768 + gr0], bb1 = b[l * 768 + gr1];

    // ---- precompute wxb[t][r] = W[r,:]@x_t + b[r] for all 128 t
    float* xf = &xb[0][0][0];                        // 8 x-rows staging (6144 floats)
    for (int c0 = 0; c0 < 128; c0 += 8) {
#pragma unroll
        for (int i = 0; i < 24; i++)
            xf[tid + 256 * i] = x_seq[(size_t)c0 * 768 + tid + 256 * i];
        __syncthreads();
#pragma unroll
        for (int tt = 0; tt < 8; tt++) {
            const float* xr = xf + tt * 768;
            float a0 = 0.f, a1 = 0.f;
#pragma unroll
            for (int k = 0; k < 24; k++) {
                float xv = xr[lane + 32 * k];
                a0 = fmaf(wv0[k], xv, a0);
                a1 = fmaf(wv1[k], xv, a1);
            }
#pragma unroll
            for (int m = 16; m >= 1; m >>= 1) {
                a0 += __shfl_xor_sync(FULLMASK, a0, m);
                a1 += __shfl_xor_sync(FULLMASK, a1, m);
            }
            if (lane == 0) {
                wxb[(c0 + tt) * 16 + r0] = a0 + bb0;
                wxb[(c0 + tt) * 16 + r1] = a1 + bb1;
            }
        }
        __syncthreads();
    }

    // ---- load persistent state: P (zeros, but read the input) and eta (or W for M)
    float p0[24], p1[24], e0a[24], e1a[24];
    const float* Pl = P_init + (size_t)l * 589824;
#pragma unroll
    for (int k = 0; k < 24; k++) {
        p0[k] = Pl[(size_t)gr0 * 768 + lane + 32 * k];
        p1[k] = Pl[(size_t)gr1 * 768 + lane + 32 * k];
    }
    const float* ep = (l == 0) ? eta0 : ((l == 2) ? eta2 : Wl);
#pragma unroll
    for (int k = 0; k < 24; k++) {
        e0a[k] = ep[(size_t)gr0 * 768 + lane + 32 * k];
        e1a[k] = ep[(size_t)gr1 * 768 + lane + 32 * k];
    }
    const float decay = 1.0f / (1.0f + __expf(-lam[l]));
    const float etasc = eta1p[0];                    // scalar eta for M layer
    const int gc0 = l * 768 + gr0;                   // column in h_cat

    // ---- preload x chunk 0 (4 steps = 3072 floats)
    {
        float* dst = &xb[0][0][0];
#pragma unroll
        for (int i = 0; i < 3; i++)
            cp_async16(dst + 4 * (tid + 256 * i), x_seq + 4 * (tid + 256 * i));
        cp_commit(); cp_wait0();
    }
    __syncthreads();

    // ---- the sequential scan: 32 chunks x 4 steps, x double-buffered via cp.async
    for (int c = 0; c < 32; c++) {
        if (c < 31) {
            const float* src = x_seq + (size_t)(c + 1) * 3072;
            float* dst = &xb[(c + 1) & 1][0][0];
#pragma unroll
            for (int i = 0; i < 3; i++)
                cp_async16(dst + 4 * (tid + 256 * i), src + 4 * (tid + 256 * i));
            cp_commit();
        }
#pragma unroll
        for (int tt = 0; tt < 4; tt++) {
            const int t = c * 4 + tt;
            const float* xr = &xb[c & 1][tt][0];
            float xv[24];
#pragma unroll
            for (int k = 0; k < 24; k++) xv[k] = xr[lane + 32 * k];  // conflict-free LDS

            float a0 = 0.f, a1 = 0.f;
            if (isM) {  // (W .* P) @ x
#pragma unroll
                for (int k = 0; k < 24; k++) {
                    a0 = fmaf(e0a[k] * p0[k], xv[k], a0);
                    a1 = fmaf(e1a[k] * p1[k], xv[k], a1);
                }
            } else {    // P @ x
#pragma unroll
                for (int k = 0; k < 24; k++) {
                    a0 = fmaf(p0[k], xv[k], a0);
                    a1 = fmaf(p1[k], xv[k], a1);
                }
            }
#pragma unroll
            for (int m = 16; m >= 1; m >>= 1) {
                a0 += __shfl_xor_sync(FULLMASK, a0, m);
                a1 += __shfl_xor_sync(FULLMASK, a1, m);
            }
            const float pre0 = a0 + wxb[t * 16 + r0];
            const float pre1 = a1 + wxb[t * 16 + r1];
            const float h0 = sigmoidf_(pre0);
            const float h1 = sigmoidf_(pre1);

            if (isM) {  // P = decay*P + eta1 * h x^T (scalar eta)
                const float f0 = etasc * h0, f1 = etasc * h1;
#pragma unroll
                for (int k = 0; k < 24; k++) {
                    p0[k] = fmaf(f0, xv[k], decay * p0[k]);
                    p1[k] = fmaf(f1, xv[k], decay * p1[k]);
                }
            } else {    // P = decay*P + eta .* (h x^T)
#pragma unroll
                for (int k = 0; k < 24; k++) {
                    p0[k] = fmaf(e0a[k], h0 * xv[k], decay * p0[k]);
                    p1[k] = fmaf(e1a[k], h1 * xv[k], decay * p1[k]);
                }
            }
            if (lane == 0) {
                g_H[t * 2304 + gc0]     = h0;
                g_H[t * 2304 + gc0 + 1] = h1;
            }
        }
        if (c < 31) cp_wait0();
        __syncthreads();
    }
}

// ---------------------------------------------------------------- kernel C: readout GEMM (split-K)
// part[kb][t][o] = sum_{j in kb-chunk} wfT[j][o] * H[t][j]
// grid (3 out-tiles of 256, 8 t-tiles of 16, 6 k-chunks of 384); 256 threads.
__global__ void __launch_bounds__(256) k_gemm() {
    __shared__ __align__(16) float Hs[7680];   // [384 j][20 pad] transposed H chunk
    const int ob = blockIdx.x, tb = blockIdx.y, kb = blockIdx.z;
    const int tid = threadIdx.x;
#pragma unroll
    for (int i = 0; i < 24; i++) {
        int idx = tid + 256 * i;               // 0..6143
        int tl = idx / 384, jl = idx - tl * 384;
        Hs[jl * 20 + tl] = g_H[(tb * 16 + tl) * 2304 + kb * 384 + jl];
    }
    __syncthreads();

    float acc[16];
#pragma unroll
    for (int i = 0; i < 16; i++) acc[i] = 0.f;

    const int o = ob * 256 + tid;
    const float* wp = g_wfT + (size_t)(kb * 384) * 768 + o;
#pragma unroll 4
    for (int j = 0; j < 384; j++) {
        float wv = wp[(size_t)j * 768];                       // coalesced LDG
        const float4* hp = (const float4*)&Hs[j * 20];        // broadcast LDS.128
#pragma unroll
        for (int u = 0; u < 4; u++) {
            float4 h4 = hp[u];
            acc[4 * u + 0] = fmaf(wv, h4.x, acc[4 * u + 0]);
            acc[4 * u + 1] = fmaf(wv, h4.y, acc[4 * u + 1]);
            acc[4 * u + 2] = fmaf(wv, h4.z, acc[4 * u + 2]);
            acc[4 * u + 3] = fmaf(wv, h4.w, acc[4 * u + 3]);
        }
    }
    float* pp = g_part + (size_t)kb * 98304;
#pragma unroll
    for (int i = 0; i < 16; i++)
        pp[(tb * 16 + i) * 768 + o] = acc[i];
}

// ---------------------------------------------------------------- kernel D: k-reduce + bias + sigmoid
__global__ void __launch_bounds__(256) k_reduce(const float* __restrict__ bf,
                                                float* __restrict__ y) {
    const int i = blockIdx.x * 256 + threadIdx.x;  // 0..98303
    float s = bf[i % 768];
#pragma unroll
    for (int k = 0; k < 6; k++) s += g_part[k * 98304 + i];
    y[i] = sigmoidf_(s);
}

// ---------------------------------------------------------------- launch
extern "C" void kernel_launch(void* const* d_in, const int* in_sizes, int n_in,
                              void* d_out, int out_size) {
    const float* x    = (const float*)d_in[0];  // (128, 768)
    const float* W    = (const float*)d_in[1];  // (3, 768, 768)
    const float* b    = (const float*)d_in[2];  // (3, 768)
    const float* lam  = (const float*)d_in[3];  // (3,)
    const float* eta0 = (const float*)d_in[4];  // (768, 768)
    const float* eta1 = (const float*)d_in[5];  // scalar
    const float* eta2 = (const float*)d_in[6];  // (768, 768)
    const float* wf   = (const float*)d_in[7];  // (768, 2304)
    const float* bf   = (const float*)d_in[8];  // (768,)
    const float* P0   = (const float*)d_in[9];  // (3, 768, 768)
    float* y = (float*)d_out;                   // (128, 768)

    k_transpose<<<dim3(72, 24), 256>>>(wf);
    k_scan<<<144, 256>>>(x, W, b, lam, eta0, eta1, eta2, P0);
    k_gemm<<<dim3(3, 8, 6), 256>>>();
    k_reduce<<<384, 256>>>(bf, y);
}

// round 2
// speedup vs baseline: 1.5333x; 1.5333x over previous
#include <cuda_runtime.h>
#include <cstddef>

#define FULLMASK 0xffffffffu
typedef unsigned long long u64;

// T=128, D=768, HID=768, L=3, OUT=768, LH=2304
__device__ float g_H[128 * 2304];        // h_cat per step
__device__ float g_wfT[2304 * 768];      // transposed w_final
__device__ float g_part[12 * 128 * 768]; // split-K partials

// ---------------------------------------------------------------- helpers
__device__ __forceinline__ unsigned smem_u32(const void* p) {
    unsigned a;
    asm("{ .reg .u64 t; cvta.to.shared.u64 t, %1; cvt.u32.u64 %0, t; }"
        : "=r"(a) : "l"(p));
    return a;
}
__device__ __forceinline__ void cp_async16(unsigned d, const void* src) {
    asm volatile("cp.async.ca.shared.global [%0], [%1], 16;\n" :: "r"(d), "l"(src));
}
__device__ __forceinline__ void cp_commit() { asm volatile("cp.async.commit_group;\n" ::); }
__device__ __forceinline__ void cp_wait0()  { asm volatile("cp.async.wait_group 0;\n" ::); }

// packed fp32x2 (Blackwell FFMA2 path — ptxas never emits from C++)
__device__ __forceinline__ u64 fma2(u64 a, u64 b, u64 c) {
    u64 d; asm("fma.rn.f32x2 %0, %1, %2, %3;" : "=l"(d) : "l"(a), "l"(b), "l"(c)); return d;
}
__device__ __forceinline__ u64 mul2(u64 a, u64 b) {
    u64 d; asm("mul.rn.f32x2 %0, %1, %2;" : "=l"(d) : "l"(a), "l"(b)); return d;
}
__device__ __forceinline__ u64 pk2(float x, float y) {
    u64 d; asm("mov.b64 %0, {%1, %2};" : "=l"(d) : "f"(x), "f"(y)); return d;
}
__device__ __forceinline__ float2 up2(u64 v) {
    float2 r; asm("mov.b64 {%0, %1}, %2;" : "=f"(r.x), "=f"(r.y) : "l"(v)); return r;
}
__device__ __forceinline__ void lds2(u64& a, u64& b, unsigned addr) {
    asm volatile("ld.shared.v2.b64 {%0, %1}, [%2];" : "=l"(a), "=l"(b) : "r"(addr));
}
__device__ __forceinline__ void ldg2(u64& a, u64& b, const float* p) {
    asm volatile("ld.global.nc.v2.b64 {%0, %1}, [%2];" : "=l"(a), "=l"(b) : "l"(p));
}
__device__ __forceinline__ float sig_fast(float z) {
    float e = __expf(-z);
    return __fdividef(1.0f, 1.0f + e);
}
__device__ __forceinline__ float wredsum(float a) {
#pragma unroll
    for (int m = 16; m >= 1; m >>= 1) a += __shfl_xor_sync(FULLMASK, a, m);
    return a;
}

// ---------------------------------------------------------------- transpose wf -> wfT
__global__ void __launch_bounds__(256) k_transpose(const float* __restrict__ wf) {
    __shared__ float tileS[64 * 65];
    const int o0 = blockIdx.x * 64;  // 12 tiles over 768
    const int j0 = blockIdx.y * 64;  // 36 tiles over 2304
    const int tid = threadIdx.x;
    const int rr = tid >> 4, cc = (tid & 15) * 4;
#pragma unroll
    for (int i = 0; i < 4; i++) {
        int r = rr + 16 * i;
        float4 v = *(const float4*)(wf + (size_t)(o0 + r) * 2304 + j0 + cc);
        tileS[r * 65 + cc + 0] = v.x; tileS[r * 65 + cc + 1] = v.y;
        tileS[r * 65 + cc + 2] = v.z; tileS[r * 65 + cc + 3] = v.w;
    }
    __syncthreads();
#pragma unroll
    for (int i = 0; i < 4; i++) {
        int jj = rr + 16 * i;
        float4 v;
        v.x = tileS[(cc + 0) * 65 + jj];
        v.y = tileS[(cc + 1) * 65 + jj];
        v.z = tileS[(cc + 2) * 65 + jj];
        v.w = tileS[(cc + 3) * 65 + jj];
        *(float4*)(g_wfT + (size_t)(j0 + jj) * 768 + o0 + cc) = v;
    }
}

// ---------------------------------------------------------------- scan inner loop (templated on layer type)
template <bool ISM>
__device__ __forceinline__ void run_scan(
    const float* __restrict__ x_seq, unsigned xbs, const float* __restrict__ wxb,
    u64 (&q0)[12], u64 (&q1)[12], const u64 (&e0)[12], const u64 (&e1)[12],
    const float* dsc, const float* idsc, u64 d42, float eta_sc,
    int tid, int lane, int r0, int gc0)
{
    // preload chunk 0 (4 steps = 3072 floats)
#pragma unroll
    for (int i = 0; i < 3; i++)
        cp_async16(xbs + 16 * (tid + 256 * i), x_seq + 4 * (tid + 256 * i));
    cp_commit(); cp_wait0();
    __syncthreads();

    for (int c = 0; c < 32; c++) {
        if (c < 31) {
            const float* src = x_seq + (size_t)(c + 1) * 3072;
            unsigned dst = xbs + ((c + 1) & 1) * 12288;
#pragma unroll
            for (int i = 0; i < 3; i++)
                cp_async16(dst + 16 * (tid + 256 * i), src + 4 * (tid + 256 * i));
            cp_commit();
        }
        const unsigned xcs = xbs + (c & 1) * 12288;
#pragma unroll
        for (int j = 0; j < 4; j++) {
            const int t = c * 4 + j;
            const unsigned xa = xcs + j * 3072 + 16 * lane;
            u64 xv[12];
#pragma unroll
            for (int kk = 0; kk < 6; kk++) lds2(xv[2 * kk], xv[2 * kk + 1], xa + 512 * kk);

            u64 a0 = 0, a1 = 0;
#pragma unroll
            for (int k = 0; k < 12; k++) {
                if (ISM) {
                    a0 = fma2(mul2(e0[k], q0[k]), xv[k], a0);
                    a1 = fma2(mul2(e1[k], q1[k]), xv[k], a1);
                } else {
                    a0 = fma2(q0[k], xv[k], a0);
                    a1 = fma2(q1[k], xv[k], a1);
                }
            }
            float2 f0 = up2(a0), f1 = up2(a1);
            float s0 = wredsum(f0.x + f0.y);
            float s1 = wredsum(f1.x + f1.y);
            const float* wx = wxb + t * 16 + r0;
            float pre0 = fmaf(dsc[j], s0, wx[0]);
            float pre1 = fmaf(dsc[j], s1, wx[1]);
            float h0 = sig_fast(pre0);
            float h1 = sig_fast(pre1);
            if (lane == 0) {
                float2 hv; hv.x = h0; hv.y = h1;
                *(float2*)(g_H + (size_t)t * 2304 + gc0) = hv;
            }
            float hh0 = h0 * idsc[j], hh1 = h1 * idsc[j];
            if (ISM) {
                float u0 = eta_sc * hh0, u1 = eta_sc * hh1;
                u64 s02 = pk2(u0, u0), s12 = pk2(u1, u1);
#pragma unroll
                for (int k = 0; k < 12; k++) {
                    q0[k] = fma2(s02, xv[k], q0[k]);
                    q1[k] = fma2(s12, xv[k], q1[k]);
                }
            } else {
                u64 h02 = pk2(hh0, hh0), h12 = pk2(hh1, hh1);
#pragma unroll
                for (int k = 0; k < 12; k++) {
                    q0[k] = fma2(e0[k], mul2(h02, xv[k]), q0[k]);
                    q1[k] = fma2(e1[k], mul2(h12, xv[k]), q1[k]);
                }
            }
        }
        // chunk-end rescale: q holds P/decay^4 -> back to P
#pragma unroll
        for (int k = 0; k < 12; k++) { q0[k] = mul2(q0[k], d42); q1[k] = mul2(q1[k], d42); }
        if (c < 31) cp_wait0();
        __syncthreads();
    }
}

// ---------------------------------------------------------------- kernel B: the scan
// 144 CTAs; CTA j: layer l=j/48, rows [(j%48)*16,+16). Warp w owns rows 2w,2w+1.
// Lane owns cols {4*lane+128*kk+q : kk<6, q<4} (float4 groups, f32x2 math).
__global__ void __launch_bounds__(256) k_scan(
    const float* __restrict__ x_seq, const float* __restrict__ W,
    const float* __restrict__ b, const float* __restrict__ lam,
    const float* __restrict__ eta0, const float* __restrict__ eta1p,
    const float* __restrict__ eta2, const float* __restrict__ P_init)
{
    __shared__ float wxb[2048];                   // [128 t][16 rows]
    __shared__ __align__(16) float xb[2][4][768]; // x double buffer / staging

    const int cta = blockIdx.x;
    const int l   = cta / 48;
    const int rb  = (cta % 48) * 16;
    const int tid = threadIdx.x;
    const int w = tid >> 5, lane = tid & 31;
    const int r0 = 2 * w;
    const int gr0 = rb + r0, gr1 = gr0 + 1;
    const float* Wl = W + (size_t)l * 589824;
    const int cb = 4 * lane;

    // ---- WXB precompute: wxb[t][r] = W[r,:]@x_t + b[r]
    u64 wv0[12], wv1[12];
#pragma unroll
    for (int kk = 0; kk < 6; kk++) {
        ldg2(wv0[2 * kk], wv0[2 * kk + 1], Wl + (size_t)gr0 * 768 + cb + 128 * kk);
        ldg2(wv1[2 * kk], wv1[2 * kk + 1], Wl + (size_t)gr1 * 768 + cb + 128 * kk);
    }
    const float bb0 = b[l * 768 + gr0], bb1 = b[l * 768 + gr1];

    float4* xf4 = (float4*)&xb[0][0][0];
    const float4* xs4 = (const float4*)x_seq;
    const unsigned xfs = smem_u32(&xb[0][0][0]);
    for (int c0 = 0; c0 < 128; c0 += 8) {
#pragma unroll
        for (int i = 0; i < 6; i++)
            xf4[tid + 256 * i] = xs4[(size_t)c0 * 192 + tid + 256 * i];
        __syncthreads();
#pragma unroll
        for (int tt = 0; tt < 8; tt++) {
            const unsigned xa = xfs + tt * 3072 + 16 * lane;
            u64 a0 = 0, a1 = 0;
#pragma unroll
            for (int kk = 0; kk < 6; kk++) {
                u64 x0, x1; lds2(x0, x1, xa + 512 * kk);
                a0 = fma2(wv0[2 * kk], x0, a0); a0 = fma2(wv0[2 * kk + 1], x1, a0);
                a1 = fma2(wv1[2 * kk], x0, a1); a1 = fma2(wv1[2 * kk + 1], x1, a1);
            }
            float2 f0 = up2(a0), f1 = up2(a1);
            float s0 = wredsum(f0.x + f0.y);
            float s1 = wredsum(f1.x + f1.y);
            if (lane == 0) {
                wxb[(c0 + tt) * 16 + r0]     = s0 + bb0;
                wxb[(c0 + tt) * 16 + r0 + 1] = s1 + bb1;
            }
        }
        __syncthreads();
    }

    // ---- persistent state
    u64 q0[12], q1[12], e0[12], e1[12];
    const float* Pl = P_init + (size_t)l * 589824;
#pragma unroll
    for (int kk = 0; kk < 6; kk++) {
        ldg2(q0[2 * kk], q0[2 * kk + 1], Pl + (size_t)gr0 * 768 + cb + 128 * kk);
        ldg2(q1[2 * kk], q1[2 * kk + 1], Pl + (size_t)gr1 * 768 + cb + 128 * kk);
    }
    const float* ep = (l == 0) ? eta0 : ((l == 2) ? eta2 : Wl);
#pragma unroll
    for (int kk = 0; kk < 6; kk++) {
        ldg2(e0[2 * kk], e0[2 * kk + 1], ep + (size_t)gr0 * 768 + cb + 128 * kk);
        ldg2(e1[2 * kk], e1[2 * kk + 1], ep + (size_t)gr1 * 768 + cb + 128 * kk);
    }
    const float decay = 1.0f / (1.0f + __expf(-lam[l]));  // one-time, precise div
    const float eta_sc = eta1p[0];
    const float d2v = decay * decay, d3v = d2v * decay, d4v = d2v * d2v;
    float dsc[4], idsc[4];
    dsc[0] = 1.f; dsc[1] = decay; dsc[2] = d2v; dsc[3] = d3v;
    idsc[0] = 1.f / decay; idsc[1] = 1.f / d2v; idsc[2] = 1.f / d3v; idsc[3] = 1.f / d4v;
    const u64 d42 = pk2(d4v, d4v);
    const int gc0 = l * 768 + rb + r0;
    const unsigned xbs = smem_u32(&xb[0][0][0]);

    if (l == 1)
        run_scan<true >(x_seq, xbs, wxb, q0, q1, e0, e1, dsc, idsc, d42, eta_sc, tid, lane, r0, gc0);
    else
        run_scan<false>(x_seq, xbs, wxb, q0, q1, e0, e1, dsc, idsc, d42, eta_sc, tid, lane, r0, gc0);
}

// ---------------------------------------------------------------- kernel C: readout GEMM (split-K 12)
// part[kb][t][o] = sum_{j in 192-chunk} wfT[j][o] * H[t][j]
// grid (3 o-tiles x 4 t-tiles x 12 k-chunks) = 144 blocks, 256 threads.
__global__ void __launch_bounds__(256) k_gemm() {
    __shared__ __align__(16) float Hs[192 * 36];  // [192 j][32 t + pad 4]
    const int ob = blockIdx.x, tb = blockIdx.y, kb = blockIdx.z;
    const int tid = threadIdx.x;
    const int t0 = tb * 32;
#pragma unroll
    for (int i = 0; i < 24; i++) {
        int idx = tid + 256 * i;               // 0..6143
        int tl = idx / 192, jl = idx - tl * 192;
        Hs[jl * 36 + tl] = g_H[(size_t)(t0 + tl) * 2304 + kb * 192 + jl];
    }
    __syncthreads();

    u64 acc[16];
#pragma unroll
    for (int i = 0; i < 16; i++) acc[i] = 0;

    const int o = ob * 256 + tid;
    const float* wp = g_wfT + (size_t)(kb * 192) * 768 + o;
    const unsigned hs = smem_u32(Hs);
#pragma unroll 8
    for (int j = 0; j < 192; j++) {
        float wv = __ldg(wp + (size_t)j * 768);     // coalesced, MLP 8 via unroll
        u64 w2 = pk2(wv, wv);
        const unsigned ha = hs + j * 144;
#pragma unroll
        for (int u = 0; u < 8; u++) {
            u64 h0, h1; lds2(h0, h1, ha + 16 * u);  // broadcast LDS.128
            acc[2 * u]     = fma2(w2, h0, acc[2 * u]);
            acc[2 * u + 1] = fma2(w2, h1, acc[2 * u + 1]);
        }
    }
    float* pp = g_part + (size_t)kb * 98304 + (size_t)t0 * 768 + o;
#pragma unroll
    for (int u = 0; u < 8; u++) {
        float2 v0 = up2(acc[2 * u]), v1 = up2(acc[2 * u + 1]);
        pp[(size_t)(4 * u + 0) * 768] = v0.x;
        pp[(size_t)(4 * u + 1) * 768] = v0.y;
        pp[(size_t)(4 * u + 2) * 768] = v1.x;
        pp[(size_t)(4 * u + 3) * 768] = v1.y;
    }
}

// ---------------------------------------------------------------- kernel D: reduce + bias + sigmoid
__global__ void __launch_bounds__(256) k_reduce(const float* __restrict__ bf,
                                                float* __restrict__ y) {
    const int i = blockIdx.x * 256 + threadIdx.x;  // float4 index, 0..24575
    const float4* b4 = (const float4*)bf;
    float4 s = b4[i % 192];
#pragma unroll
    for (int k = 0; k < 12; k++) {
        float4 p = *(const float4*)(g_part + (size_t)k * 98304 + 4 * (size_t)i);
        s.x += p.x; s.y += p.y; s.z += p.z; s.w += p.w;
    }
    float4 r;
    r.x = sig_fast(s.x); r.y = sig_fast(s.y);
    r.z = sig_fast(s.z); r.w = sig_fast(s.w);
    ((float4*)y)[i] = r;
}

// ---------------------------------------------------------------- launch
extern "C" void kernel_launch(void* const* d_in, const int* in_sizes, int n_in,
                              void* d_out, int out_size) {
    const float* x    = (const float*)d_in[0];  // (128, 768)
    const float* W    = (const float*)d_in[1];  // (3, 768, 768)
    const float* b    = (const float*)d_in[2];  // (3, 768)
    const float* lam  = (const float*)d_in[3];  // (3,)
    const float* eta0 = (const float*)d_in[4];  // (768, 768)
    const float* eta1 = (const float*)d_in[5];  // scalar
    const float* eta2 = (const float*)d_in[6];  // (768, 768)
    const float* wf   = (const float*)d_in[7];  // (768, 2304)
    const float* bf   = (const float*)d_in[8];  // (768,)
    const float* P0   = (const float*)d_in[9];  // (3, 768, 768)
    float* y = (float*)d_out;                   // (128, 768)

    k_transpose<<<dim3(12, 36), 256>>>(wf);
    k_scan<<<144, 256>>>(x, W, b, lam, eta0, eta1, eta2, P0);
    k_gemm<<<dim3(3, 4, 12), 256>>>();
    k_reduce<<<96, 256>>>(bf, y);
}